// round 13
// baseline (speedup 1.0000x reference)
#include <cuda_runtime.h>

// Problem constants
#define BB   32
#define QHH  32
#define KVHH 8
#define DD   128
#define PP   4096
#define NN   4096       // QHH*DD
#define KNN  1024       // KVHH*DD
#define GG   4          // QHH/KVHH
#define ROWS_TOT 6144   // NN + 2*KNN
#define KSPLIT 32
#define NCHUNK 16
#define CHUNK_S (PP / NCHUNK)   // 256 rows per chunk
#define SROW (KVHH*DD)          // 1024 floats stride over s in cache
#define QW   32                 // K staging quarter width (dims)
#define KPAD 36                 // padded row width for staging buffers

// Scratch (device globals; no allocations allowed)
__device__ float g_xnorm[BB * NN];
__device__ float g_gpart[KSPLIT][BB * ROWS_TOT];
__device__ float g_qkv[BB * ROWS_TOT];
__device__ float g_pnum[BB * KVHH * NCHUNK][GG * DD];
__device__ float g_pden[BB * KVHH * NCHUNK][GG];

// ---- helpers: packed f32x2 FMA, cp.async ----------------------------------
__device__ __forceinline__ void fma2(unsigned long long& d,
                                     unsigned long long a,
                                     unsigned long long b) {
    asm("fma.rn.f32x2 %0, %1, %2, %3;" : "=l"(d) : "l"(a), "l"(b), "l"(d));
}
__device__ __forceinline__ unsigned long long pack2(float x, float y) {
    unsigned long long r;
    asm("mov.b64 %0, {%1, %2};" : "=l"(r) : "f"(x), "f"(y));
    return r;
}
__device__ __forceinline__ float2 unpack2(unsigned long long v) {
    float2 r;
    asm("mov.b64 {%0, %1}, %2;" : "=f"(r.x), "=f"(r.y) : "l"(v));
    return r;
}
__device__ __forceinline__ void cp_async16(void* smem_dst, const void* gsrc) {
    unsigned s = (unsigned)__cvta_generic_to_shared(smem_dst);
    asm volatile("cp.async.cg.shared.global [%0], [%1], 16;\n" :: "r"(s), "l"(gsrc));
}
#define CP_COMMIT() asm volatile("cp.async.commit_group;\n" ::: "memory")
#define CP_WAIT1()  asm volatile("cp.async.wait_group 1;\n" ::: "memory")
#define CP_WAIT0()  asm volatile("cp.async.wait_group 0;\n" ::: "memory")

// streaming (evict-first) 16B load: V has zero reuse
__device__ __forceinline__ ulonglong2 ldcs16(const void* p) {
    ulonglong2 r;
    asm volatile("ld.global.cs.v2.u64 {%0, %1}, [%2];"
                 : "=l"(r.x), "=l"(r.y) : "l"(p));
    return r;
}

// ---------------------------------------------------------------------------
// 1) RMSNorm
// ---------------------------------------------------------------------------
__global__ void rms_kernel(const float* __restrict__ X) {
    int b = blockIdx.x;
    int t = threadIdx.x;  // 256
    const float4* x4 = (const float4*)(X + (size_t)b * NN);
    float ss = 0.f;
    for (int i = t; i < NN / 4; i += 256) {
        float4 a = x4[i];
        ss += a.x * a.x + a.y * a.y + a.z * a.z + a.w * a.w;
    }
    __shared__ float red[256];
    red[t] = ss;
    __syncthreads();
    for (int o = 128; o > 0; o >>= 1) {
        if (t < o) red[t] += red[t + o];
        __syncthreads();
    }
    float scale = rsqrtf(red[0] / (float)NN);
    float4* o4 = (float4*)(g_xnorm + (size_t)b * NN);
    for (int i = t; i < NN / 4; i += 256) {
        float4 a = x4[i];
        a.x *= scale; a.y *= scale; a.z *= scale; a.w *= scale;
        o4[i] = a;
    }
}

// ---------------------------------------------------------------------------
// 2) QKV projection (K-split GEMM) — packed f32x2 FMA inner loop.
//    KSPLIT=32 -> 1536 blocks -> >=5 waves (kills the 1.3-wave tail).
// ---------------------------------------------------------------------------
#define TKC 64
__global__ void qkv_kernel(const float* __restrict__ Wq,
                           const float* __restrict__ Wk,
                           const float* __restrict__ Wv) {
    int rtile = blockIdx.x;   // 0..47
    int ks    = blockIdx.y;   // 0..KSPLIT-1
    int tid   = threadIdx.x;  // 256
    int r0 = rtile * 128;
    const float* Wbase;
    if (r0 < NN)            Wbase = Wq + (size_t)r0 * NN;
    else if (r0 < NN + KNN) Wbase = Wk + (size_t)(r0 - NN) * NN;
    else                    Wbase = Wv + (size_t)(r0 - NN - KNN) * NN;
    int k0 = ks * (NN / KSPLIT);  // 128-wide K slice

    __shared__ __align__(16) float xs[BB][TKC + 4];    // pad 68
    __shared__ __align__(16) float ws[128][TKC + 4];

    int rq = tid & 31;
    int bq = tid >> 5;

    unsigned long long acc2[4][4];
#pragma unroll
    for (int i = 0; i < 4; i++)
#pragma unroll
        for (int j = 0; j < 4; j++) acc2[i][j] = 0ull;

    for (int kc = 0; kc < NN / KSPLIT; kc += TKC) {
#pragma unroll
        for (int i = 0; i < 2; i++) {
            int idx = tid + 256 * i;
            int bb = idx >> 4, c = idx & 15;
            float4 v = *(const float4*)(g_xnorm + (size_t)bb * NN + k0 + kc + c * 4);
            *(float4*)&xs[bb][c * 4] = v;
        }
#pragma unroll
        for (int i = 0; i < 8; i++) {
            int idx = tid + 256 * i;
            int r = idx >> 4, c = idx & 15;
            float4 v = *(const float4*)(Wbase + (size_t)r * NN + k0 + kc + c * 4);
            *(float4*)&ws[r][c * 4] = v;
        }
        __syncthreads();
#pragma unroll
        for (int kk = 0; kk < TKC; kk += 4) {
            ulonglong2 xv[4], wv[4];
#pragma unroll
            for (int i = 0; i < 4; i++) xv[i] = *(const ulonglong2*)&xs[bq * 4 + i][kk];
#pragma unroll
            for (int j = 0; j < 4; j++) wv[j] = *(const ulonglong2*)&ws[rq + 32 * j][kk];
#pragma unroll
            for (int i = 0; i < 4; i++)
#pragma unroll
                for (int j = 0; j < 4; j++) {
                    fma2(acc2[i][j], xv[i].x, wv[j].x);
                    fma2(acc2[i][j], xv[i].y, wv[j].y);
                }
        }
        __syncthreads();
    }
#pragma unroll
    for (int i = 0; i < 4; i++) {
        int bb = bq * 4 + i;
#pragma unroll
        for (int j = 0; j < 4; j++) {
            int r = r0 + rq + 32 * j;
            float2 p = unpack2(acc2[i][j]);
            g_gpart[ks][(size_t)bb * ROWS_TOT + r] = p.x + p.y;
        }
    }
}

__global__ void qkv_reduce() {
    int idx = blockIdx.x * 256 + threadIdx.x;
    float s = 0.f;
#pragma unroll
    for (int ks = 0; ks < KSPLIT; ks++) s += g_gpart[ks][idx];
    g_qkv[idx] = s;
}

// ---------------------------------------------------------------------------
// 3) Split-KV attention. K staged via double-buffered cp.async in 32-dim
//    quarters; V streamed direct with .cs (evict-first). Non-stabilized
//    softmax is linear over S-partitions -> exact split-KV partials.
// ---------------------------------------------------------------------------
__global__ void __launch_bounds__(128, 4)
attn_kernel(const float* __restrict__ cK, const float* __restrict__ cV) {
    int c   = blockIdx.x;   // chunk
    int kvh = blockIdx.y;   // 0..7
    int b   = blockIdx.z;   // 0..31
    int t   = threadIdx.x;  // 128
    int c4  = t & 31;       // dim float4 index (phase B)
    int rg  = t >> 5;       // row subgroup / warp id
    int lane = t & 31;

    __shared__ __align__(16) float ksm[2][128][KPAD]; // 36864 B
    __shared__ __align__(16) float qs[GG][DD];        // 2048 B
    __shared__ __align__(16) float4 Es4[128];         // 2048 B
    __shared__ __align__(16) float redO[4][GG][DD];   // 8192 B => 49152 total
    float* sredW = (float*)&Es4[64];                  // aliased: dead when used

    for (int i = t; i < GG * DD; i += 128) {
        int g = i >> 7, d = i & 127;
        qs[g][d] = g_qkv[(size_t)b * ROWS_TOT + (kvh * GG + g) * DD + d];
    }

    const size_t baseK = ((size_t)b * PP) * SROW + (size_t)kvh * DD;
    // quarter-load geometry: 128 rows x 8 float4; thread covers rows lr+16i
    const int lr = t >> 3, lc = (t & 7) * 4;

    unsigned long long O0a=0,O0b=0,O1a=0,O1b=0,O2a=0,O2b=0,O3a=0,O3b=0;
    float dent0 = 0.f, dent1 = 0.f, dent2 = 0.f, dent3 = 0.f;

    const int s_begin = c * CHUNK_S, s_end = s_begin + CHUNK_S;

    // prologue: issue quarter 0 of first tile into buffer 0
    {
        const float* src = cK + baseK + (size_t)(s_begin + lr) * SROW + lc;
        float* dst = &ksm[0][lr][lc];
#pragma unroll
        for (int i = 0; i < 8; i++)
            cp_async16(dst + i * 16 * KPAD, src + (size_t)i * 16 * SROW);
        CP_COMMIT();
    }

    int buf = 0;  // buffer holding the quarter about to be consumed
    for (int t0 = s_begin; t0 < s_end; t0 += 128) {
        unsigned long long sca0 = 0ull, sca1 = 0ull, sca2 = 0ull, sca3 = 0ull;
#pragma unroll
        for (int q = 0; q < 4; q++) {
            bool last = (t0 + 128 >= s_end) && (q == 3);
            if (!last) {
                int nt0 = (q == 3) ? t0 + 128 : t0;
                int nq  = (q == 3) ? 0 : q + 1;
                const float* src = cK + baseK + (size_t)(nt0 + lr) * SROW
                                   + nq * QW + lc;
                float* dst = &ksm[buf ^ 1][lr][lc];
#pragma unroll
                for (int i = 0; i < 8; i++)
                    cp_async16(dst + i * 16 * KPAD, src + (size_t)i * 16 * SROW);
                CP_COMMIT();
                CP_WAIT1();
            } else {
                CP_WAIT0();
            }
            __syncthreads();
            // scores on quarter q (dims q*32 .. q*32+31) from ksm[buf]
#pragma unroll
            for (int d4 = 0; d4 < 8; d4++) {
                ulonglong2 k2 = *(const ulonglong2*)&ksm[buf][t][d4 * 4];
                int dq = q * QW + d4 * 4;
                ulonglong2 q0 = *(const ulonglong2*)&qs[0][dq];
                ulonglong2 q1 = *(const ulonglong2*)&qs[1][dq];
                ulonglong2 q2 = *(const ulonglong2*)&qs[2][dq];
                ulonglong2 q3 = *(const ulonglong2*)&qs[3][dq];
                fma2(sca0, k2.x, q0.x); fma2(sca0, k2.y, q0.y);
                fma2(sca1, k2.x, q1.x); fma2(sca1, k2.y, q1.y);
                fma2(sca2, k2.x, q2.x); fma2(sca2, k2.y, q2.y);
                fma2(sca3, k2.x, q3.x); fma2(sca3, k2.y, q3.y);
            }
            __syncthreads();
            buf ^= 1;
        }

        float2 p0 = unpack2(sca0), p1 = unpack2(sca1),
               p2 = unpack2(sca2), p3 = unpack2(sca3);
        float4 e;
        e.x = __expf(p0.x + p0.y); e.y = __expf(p1.x + p1.y);
        e.z = __expf(p2.x + p2.y); e.w = __expf(p3.x + p3.y);
        dent0 += e.x; dent1 += e.y; dent2 += e.z; dent3 += e.w;
        Es4[t] = e;
        __syncthreads();

        // ---- Phase B: V accumulation (packed, streaming), rows rg+4j ----
        // 4-row stride = 4*SROW floats = SROW 16B-elements.
        const ulonglong2* V2 = (const ulonglong2*)
            (cV + baseK + (size_t)(t0 + rg) * SROW) + c4;
#pragma unroll 8
        for (int j = 0; j < 32; j++) {
            ulonglong2 v2 = ldcs16(V2 + (size_t)j * SROW); // +4 rows per j
            float4 f = Es4[rg + 4 * j];                    // warp-uniform bcast
            unsigned long long fx = pack2(f.x, f.x);
            unsigned long long fy = pack2(f.y, f.y);
            unsigned long long fz = pack2(f.z, f.z);
            unsigned long long fw = pack2(f.w, f.w);
            fma2(O0a, fx, v2.x); fma2(O0b, fx, v2.y);
            fma2(O1a, fy, v2.x); fma2(O1b, fy, v2.y);
            fma2(O2a, fz, v2.x); fma2(O2b, fz, v2.y);
            fma2(O3a, fw, v2.x); fma2(O3b, fw, v2.y);
        }
        __syncthreads();
    }

    // unpack accumulators
    float o[GG][4];
    { float2 a = unpack2(O0a), b2 = unpack2(O0b);
      o[0][0]=a.x; o[0][1]=a.y; o[0][2]=b2.x; o[0][3]=b2.y; }
    { float2 a = unpack2(O1a), b2 = unpack2(O1b);
      o[1][0]=a.x; o[1][1]=a.y; o[1][2]=b2.x; o[1][3]=b2.y; }
    { float2 a = unpack2(O2a), b2 = unpack2(O2b);
      o[2][0]=a.x; o[2][1]=a.y; o[2][2]=b2.x; o[2][3]=b2.y; }
    { float2 a = unpack2(O3a), b2 = unpack2(O3b);
      o[3][0]=a.x; o[3][1]=a.y; o[3][2]=b2.x; o[3][3]=b2.y; }

    // Appended row s = P (k_new/v_new): last chunk only
    if (c == NCHUNK - 1) {
        if (t == 0) {
            const float* kn = g_qkv + (size_t)b * ROWS_TOT + NN + kvh * DD;
            float4 e;
            float* ep = &e.x;
#pragma unroll
            for (int g = 0; g < GG; g++) {
                float s0 = 0.f, s1 = 0.f, s2 = 0.f, s3 = 0.f;
                for (int d = 0; d < DD; d += 4) {
                    s0 += qs[g][d + 0] * kn[d + 0];
                    s1 += qs[g][d + 1] * kn[d + 1];
                    s2 += qs[g][d + 2] * kn[d + 2];
                    s3 += qs[g][d + 3] * kn[d + 3];
                }
                ep[g] = __expf(s0 + s1 + s2 + s3);
            }
            Es4[0] = e;
            dent0 += e.x; dent1 += e.y; dent2 += e.z; dent3 += e.w;
        }
        __syncthreads();
        if (rg == 0) {  // exactly one subgroup adds the appended row
            float4 v = *(const float4*)(g_qkv + (size_t)b * ROWS_TOT + NN + KNN
                                        + kvh * DD + c4 * 4);
            float4 f = Es4[0];
#pragma unroll
            for (int d = 0; d < 4; d++) {
                float vd = (&v.x)[d];
                o[0][d] += f.x * vd; o[1][d] += f.y * vd;
                o[2][d] += f.z * vd; o[3][d] += f.w * vd;
            }
        }
        __syncthreads();
    }

    // Denominators: shfl-reduce within warp
    for (int off = 16; off > 0; off >>= 1) {
        dent0 += __shfl_xor_sync(0xffffffffu, dent0, off);
        dent1 += __shfl_xor_sync(0xffffffffu, dent1, off);
        dent2 += __shfl_xor_sync(0xffffffffu, dent2, off);
        dent3 += __shfl_xor_sync(0xffffffffu, dent3, off);
    }
    if (lane == 0) {
        sredW[rg * 4 + 0] = dent0; sredW[rg * 4 + 1] = dent1;
        sredW[rg * 4 + 2] = dent2; sredW[rg * 4 + 3] = dent3;
    }
    int d0 = c4 * 4;
#pragma unroll
    for (int g = 0; g < GG; g++) {
        redO[rg][g][d0+0] = o[g][0]; redO[rg][g][d0+1] = o[g][1];
        redO[rg][g][d0+2] = o[g][2]; redO[rg][g][d0+3] = o[g][3];
    }
    __syncthreads();

    int pb = ((b * KVHH) + kvh) * NCHUNK + c;
    if (t < GG) {
        g_pden[pb][t] = sredW[0 * 4 + t] + sredW[1 * 4 + t]
                      + sredW[2 * 4 + t] + sredW[3 * 4 + t];
    }
#pragma unroll
    for (int g = 0; g < GG; g++) {
        float num = redO[0][g][t] + redO[1][g][t] + redO[2][g][t] + redO[3][g][t];
        g_pnum[pb][g * DD + t] = num;
    }
}

// ---------------------------------------------------------------------------
// 4) Epilogue: sum chunk partials, divide, write [B, N]
// ---------------------------------------------------------------------------
__global__ void attn_epilogue(float* __restrict__ out) {
    int bk = blockIdx.x;   // b*KVHH + kvh
    int t  = threadIdx.x;  // 128
    int b = bk / KVHH, kvh = bk % KVHH;
#pragma unroll
    for (int g = 0; g < GG; g++) {
        float num = 0.f, den = 0.f;
#pragma unroll
        for (int c = 0; c < NCHUNK; c++) {
            int pb = bk * NCHUNK + c;
            num += g_pnum[pb][g * DD + t];
            den += g_pden[pb][g];
        }
        out[(size_t)b * NN + (kvh * GG + g) * DD + t] = num / den;
    }
}

// ---------------------------------------------------------------------------
extern "C" void kernel_launch(void* const* d_in, const int* in_sizes, int n_in,
                              void* d_out, int out_size) {
    const float* X  = (const float*)d_in[0];
    const float* Wq = (const float*)d_in[1];
    const float* Wk = (const float*)d_in[2];
    const float* Wv = (const float*)d_in[3];
    const float* cK = (const float*)d_in[4];
    const float* cV = (const float*)d_in[5];
    float* out = (float*)d_out;

    rms_kernel<<<BB, 256>>>(X);
    qkv_kernel<<<dim3(ROWS_TOT / 128, KSPLIT), 256>>>(Wq, Wk, Wv);
    qkv_reduce<<<(BB * ROWS_TOT) / 256, 256>>>();
    attn_kernel<<<dim3(NCHUNK, KVHH, BB), 128>>>(cK, cV);
    attn_epilogue<<<BB * KVHH, 128>>>(out);
}

// round 14
// speedup vs baseline: 1.0708x; 1.0708x over previous
#include <cuda_runtime.h>

// Problem constants
#define BB   32
#define QHH  32
#define KVHH 8
#define DD   128
#define PP   4096
#define NN   4096       // QHH*DD
#define KNN  1024       // KVHH*DD
#define GG   4          // QHH/KVHH
#define ROWS_TOT 6144   // NN + 2*KNN
#define KSPLIT 8
#define NCHUNK 16
#define CHUNK_S (PP / NCHUNK)   // 256 rows per chunk
#define SROW (KVHH*DD)          // 1024 floats stride over s in cache
#define QW   32                 // K staging quarter width (dims)
#define KPAD 36                 // padded row width for staging buffers

// Scratch (device globals; no allocations allowed)
__device__ float g_scale[BB];                           // rms scales
__device__ float g_gpart[KSPLIT][BB * ROWS_TOT];        // qkv partials (6 MB)
__device__ float g_pnum[BB * KVHH * NCHUNK][GG * DD];
__device__ float g_pden[BB * KVHH * NCHUNK][GG];

// ---- helpers: packed f32x2 FMA, cp.async ----------------------------------
__device__ __forceinline__ void fma2(unsigned long long& d,
                                     unsigned long long a,
                                     unsigned long long b) {
    asm("fma.rn.f32x2 %0, %1, %2, %3;" : "=l"(d) : "l"(a), "l"(b), "l"(d));
}
__device__ __forceinline__ unsigned long long pack2(float x, float y) {
    unsigned long long r;
    asm("mov.b64 %0, {%1, %2};" : "=l"(r) : "f"(x), "f"(y));
    return r;
}
__device__ __forceinline__ float2 unpack2(unsigned long long v) {
    float2 r;
    asm("mov.b64 {%0, %1}, %2;" : "=f"(r.x), "=f"(r.y) : "l"(v));
    return r;
}
__device__ __forceinline__ void cp_async16(void* smem_dst, const void* gsrc) {
    unsigned s = (unsigned)__cvta_generic_to_shared(smem_dst);
    asm volatile("cp.async.cg.shared.global [%0], [%1], 16;\n" :: "r"(s), "l"(gsrc));
}
#define CP_COMMIT() asm volatile("cp.async.commit_group;\n" ::: "memory")
#define CP_WAIT1()  asm volatile("cp.async.wait_group 1;\n" ::: "memory")
#define CP_WAIT0()  asm volatile("cp.async.wait_group 0;\n" ::: "memory")

// ---------------------------------------------------------------------------
// 1) RMS scales only: g_scale[b] = rsqrt(mean(X[b]^2))
// ---------------------------------------------------------------------------
__global__ void rms_kernel(const float* __restrict__ X) {
    int b = blockIdx.x;
    int t = threadIdx.x;  // 256
    const float4* x4 = (const float4*)(X + (size_t)b * NN);
    float ss = 0.f;
    for (int i = t; i < NN / 4; i += 256) {
        float4 a = x4[i];
        ss += a.x * a.x + a.y * a.y + a.z * a.z + a.w * a.w;
    }
    __shared__ float red[256];
    red[t] = ss;
    __syncthreads();
    for (int o = 128; o > 0; o >>= 1) {
        if (t < o) red[t] += red[t + o];
        __syncthreads();
    }
    if (t == 0) g_scale[b] = rsqrtf(red[0] / (float)NN);
}

// ---------------------------------------------------------------------------
// 2) QKV projection (K-split GEMM): reads X directly, scales on load.
// ---------------------------------------------------------------------------
#define TKC 64
__global__ void qkv_kernel(const float* __restrict__ X,
                           const float* __restrict__ Wq,
                           const float* __restrict__ Wk,
                           const float* __restrict__ Wv) {
    int rtile = blockIdx.x;   // 0..47
    int ks    = blockIdx.y;   // 0..7
    int tid   = threadIdx.x;  // 256
    int r0 = rtile * 128;
    const float* Wbase;
    if (r0 < NN)            Wbase = Wq + (size_t)r0 * NN;
    else if (r0 < NN + KNN) Wbase = Wk + (size_t)(r0 - NN) * NN;
    else                    Wbase = Wv + (size_t)(r0 - NN - KNN) * NN;
    int k0 = ks * (NN / KSPLIT);  // 512-wide K slice

    __shared__ __align__(16) float xs[BB][TKC + 4];    // pad 68
    __shared__ __align__(16) float ws[128][TKC + 4];

    int rq = tid & 31;
    int bq = tid >> 5;

    unsigned long long acc2[4][4];
#pragma unroll
    for (int i = 0; i < 4; i++)
#pragma unroll
        for (int j = 0; j < 4; j++) acc2[i][j] = 0ull;

    for (int kc = 0; kc < NN / KSPLIT; kc += TKC) {
#pragma unroll
        for (int i = 0; i < 2; i++) {
            int idx = tid + 256 * i;
            int bb = idx >> 4, c = idx & 15;
            float s = g_scale[bb];
            float4 v = *(const float4*)(X + (size_t)bb * NN + k0 + kc + c * 4);
            v.x *= s; v.y *= s; v.z *= s; v.w *= s;
            *(float4*)&xs[bb][c * 4] = v;
        }
#pragma unroll
        for (int i = 0; i < 8; i++) {
            int idx = tid + 256 * i;
            int r = idx >> 4, c = idx & 15;
            float4 v = *(const float4*)(Wbase + (size_t)r * NN + k0 + kc + c * 4);
            *(float4*)&ws[r][c * 4] = v;
        }
        __syncthreads();
#pragma unroll
        for (int kk = 0; kk < TKC; kk += 4) {
            ulonglong2 xv[4], wv[4];
#pragma unroll
            for (int i = 0; i < 4; i++) xv[i] = *(const ulonglong2*)&xs[bq * 4 + i][kk];
#pragma unroll
            for (int j = 0; j < 4; j++) wv[j] = *(const ulonglong2*)&ws[rq + 32 * j][kk];
#pragma unroll
            for (int i = 0; i < 4; i++)
#pragma unroll
                for (int j = 0; j < 4; j++) {
                    fma2(acc2[i][j], xv[i].x, wv[j].x);
                    fma2(acc2[i][j], xv[i].y, wv[j].y);
                }
        }
        __syncthreads();
    }
#pragma unroll
    for (int i = 0; i < 4; i++) {
        int bb = bq * 4 + i;
#pragma unroll
        for (int j = 0; j < 4; j++) {
            int r = r0 + rq + 32 * j;
            float2 p = unpack2(acc2[i][j]);
            g_gpart[ks][(size_t)bb * ROWS_TOT + r] = p.x + p.y;
        }
    }
}

// ---------------------------------------------------------------------------
// 3) Split-KV attention. K double-buffered via cp.async in 32-dim quarters.
//    qs / appended k,v are summed from the KSPLIT partials here (no reduce
//    kernel). Non-stabilized softmax is linear over S-partitions.
// ---------------------------------------------------------------------------
__global__ void __launch_bounds__(128, 4)
attn_kernel(const float* __restrict__ cK, const float* __restrict__ cV) {
    int c   = blockIdx.x;   // chunk
    int kvh = blockIdx.y;   // 0..7
    int b   = blockIdx.z;   // 0..31
    int t   = threadIdx.x;  // 128
    int c4  = t & 31;       // dim float4 index (phase B)
    int rg  = t >> 5;       // row subgroup / warp id
    int lane = t & 31;

    __shared__ __align__(16) float ksm[2][128][KPAD]; // 36864 B
    __shared__ __align__(16) float qs[GG][DD];        // 2048 B
    __shared__ __align__(16) float4 Es4[128];         // 2048 B
    __shared__ __align__(16) float redO[4][GG][DD];   // 8192 B => 49152 total
    float* sredW = (float*)&Es4[64];                  // aliased: dead when used
    // appended-row buffers aliased into ksm (dead after the main loop)
    float* knb  = &ksm[0][0][0];
    float* vnb  = &ksm[0][0][0] + DD;
    float* enew = &ksm[1][0][0];

    // qs = sum of KSPLIT partials (gpart is small; L2-resident)
    for (int i = t; i < GG * DD; i += 128) {
        int g = i >> 7, d = i & 127;
        size_t base = (size_t)b * ROWS_TOT + (kvh * GG + g) * DD + d;
        float s = 0.f;
#pragma unroll
        for (int ks2 = 0; ks2 < KSPLIT; ks2++) s += g_gpart[ks2][base];
        qs[g][d] = s;
    }

    const size_t baseK = ((size_t)b * PP) * SROW + (size_t)kvh * DD;
    // quarter-load geometry: 128 rows x 8 float4; thread covers rows lr+16i
    const int lr = t >> 3, lc = (t & 7) * 4;

    unsigned long long O0a=0,O0b=0,O1a=0,O1b=0,O2a=0,O2b=0,O3a=0,O3b=0;
    float dent0 = 0.f, dent1 = 0.f, dent2 = 0.f, dent3 = 0.f;

    const int s_begin = c * CHUNK_S, s_end = s_begin + CHUNK_S;

    // prologue: issue quarter 0 of first tile into buffer 0
    {
        const float* src = cK + baseK + (size_t)(s_begin + lr) * SROW + lc;
        float* dst = &ksm[0][lr][lc];
#pragma unroll
        for (int i = 0; i < 8; i++)
            cp_async16(dst + i * 16 * KPAD, src + (size_t)i * 16 * SROW);
        CP_COMMIT();
    }

    int buf = 0;  // buffer holding the quarter about to be consumed
    for (int t0 = s_begin; t0 < s_end; t0 += 128) {
        unsigned long long sca0 = 0ull, sca1 = 0ull, sca2 = 0ull, sca3 = 0ull;
#pragma unroll
        for (int q = 0; q < 4; q++) {
            bool last = (t0 + 128 >= s_end) && (q == 3);
            if (!last) {
                int nt0 = (q == 3) ? t0 + 128 : t0;
                int nq  = (q == 3) ? 0 : q + 1;
                const float* src = cK + baseK + (size_t)(nt0 + lr) * SROW
                                   + nq * QW + lc;
                float* dst = &ksm[buf ^ 1][lr][lc];
#pragma unroll
                for (int i = 0; i < 8; i++)
                    cp_async16(dst + i * 16 * KPAD, src + (size_t)i * 16 * SROW);
                CP_COMMIT();
                CP_WAIT1();
            } else {
                CP_WAIT0();
            }
            __syncthreads();
            // scores on quarter q (dims q*32 .. q*32+31) from ksm[buf]
#pragma unroll
            for (int d4 = 0; d4 < 8; d4++) {
                ulonglong2 k2 = *(const ulonglong2*)&ksm[buf][t][d4 * 4];
                int dq = q * QW + d4 * 4;
                ulonglong2 q0 = *(const ulonglong2*)&qs[0][dq];
                ulonglong2 q1 = *(const ulonglong2*)&qs[1][dq];
                ulonglong2 q2 = *(const ulonglong2*)&qs[2][dq];
                ulonglong2 q3 = *(const ulonglong2*)&qs[3][dq];
                fma2(sca0, k2.x, q0.x); fma2(sca0, k2.y, q0.y);
                fma2(sca1, k2.x, q1.x); fma2(sca1, k2.y, q1.y);
                fma2(sca2, k2.x, q2.x); fma2(sca2, k2.y, q2.y);
                fma2(sca3, k2.x, q3.x); fma2(sca3, k2.y, q3.y);
            }
            __syncthreads();
            buf ^= 1;
        }

        float2 p0 = unpack2(sca0), p1 = unpack2(sca1),
               p2 = unpack2(sca2), p3 = unpack2(sca3);
        float4 e;
        e.x = __expf(p0.x + p0.y); e.y = __expf(p1.x + p1.y);
        e.z = __expf(p2.x + p2.y); e.w = __expf(p3.x + p3.y);
        dent0 += e.x; dent1 += e.y; dent2 += e.z; dent3 += e.w;
        Es4[t] = e;
        __syncthreads();

        // ---- Phase B: V accumulation (packed), rows rg+4j, dims c4*4.. ----
        // 4-row stride = 4*SROW floats = SROW 16B-elements.
        const ulonglong2* V2 = (const ulonglong2*)
            (cV + baseK + (size_t)(t0 + rg) * SROW) + c4;
#pragma unroll 8
        for (int j = 0; j < 32; j++) {
            ulonglong2 v2 = V2[(size_t)j * SROW];        // +4 rows per j
            float4 f = Es4[rg + 4 * j];                  // warp-uniform broadcast
            unsigned long long fx = pack2(f.x, f.x);
            unsigned long long fy = pack2(f.y, f.y);
            unsigned long long fz = pack2(f.z, f.z);
            unsigned long long fw = pack2(f.w, f.w);
            fma2(O0a, fx, v2.x); fma2(O0b, fx, v2.y);
            fma2(O1a, fy, v2.x); fma2(O1b, fy, v2.y);
            fma2(O2a, fz, v2.x); fma2(O2b, fz, v2.y);
            fma2(O3a, fw, v2.x); fma2(O3b, fw, v2.y);
        }
        __syncthreads();
    }

    // unpack accumulators
    float o[GG][4];
    { float2 a = unpack2(O0a), b2 = unpack2(O0b);
      o[0][0]=a.x; o[0][1]=a.y; o[0][2]=b2.x; o[0][3]=b2.y; }
    { float2 a = unpack2(O1a), b2 = unpack2(O1b);
      o[1][0]=a.x; o[1][1]=a.y; o[1][2]=b2.x; o[1][3]=b2.y; }
    { float2 a = unpack2(O2a), b2 = unpack2(O2b);
      o[2][0]=a.x; o[2][1]=a.y; o[2][2]=b2.x; o[2][3]=b2.y; }
    { float2 a = unpack2(O3a), b2 = unpack2(O3b);
      o[3][0]=a.x; o[3][1]=a.y; o[3][2]=b2.x; o[3][3]=b2.y; }

    // Appended row s = P (k_new/v_new): last chunk only. ksm is dead now.
    if (c == NCHUNK - 1) {
        size_t bk = (size_t)b * ROWS_TOT + NN + kvh * DD + t;
        float sk = 0.f, sv = 0.f;
#pragma unroll
        for (int ks2 = 0; ks2 < KSPLIT; ks2++) {
            sk += g_gpart[ks2][bk];
            sv += g_gpart[ks2][bk + KNN];
        }
        knb[t] = sk;
        vnb[t] = sv;
        __syncthreads();
        // warp rg computes the score for head-group rg via shfl reduce
        float part = qs[rg][lane]        * knb[lane]
                   + qs[rg][lane + 32]   * knb[lane + 32]
                   + qs[rg][lane + 64]   * knb[lane + 64]
                   + qs[rg][lane + 96]   * knb[lane + 96];
        for (int off = 16; off > 0; off >>= 1)
            part += __shfl_xor_sync(0xffffffffu, part, off);
        float e = __expf(part);
        if (lane == 0) enew[rg] = e;
        __syncthreads();
        if (t == 0) {
            dent0 += enew[0]; dent1 += enew[1];
            dent2 += enew[2]; dent3 += enew[3];
        }
        if (rg == 0) {  // exactly one subgroup adds the appended row
            float f0 = enew[0], f1 = enew[1], f2 = enew[2], f3 = enew[3];
#pragma unroll
            for (int d = 0; d < 4; d++) {
                float vd = vnb[c4 * 4 + d];
                o[0][d] += f0 * vd; o[1][d] += f1 * vd;
                o[2][d] += f2 * vd; o[3][d] += f3 * vd;
            }
        }
        __syncthreads();
    }

    // Denominators: shfl-reduce within warp
    for (int off = 16; off > 0; off >>= 1) {
        dent0 += __shfl_xor_sync(0xffffffffu, dent0, off);
        dent1 += __shfl_xor_sync(0xffffffffu, dent1, off);
        dent2 += __shfl_xor_sync(0xffffffffu, dent2, off);
        dent3 += __shfl_xor_sync(0xffffffffu, dent3, off);
    }
    if (lane == 0) {
        sredW[rg * 4 + 0] = dent0; sredW[rg * 4 + 1] = dent1;
        sredW[rg * 4 + 2] = dent2; sredW[rg * 4 + 3] = dent3;
    }
    int d0 = c4 * 4;
#pragma unroll
    for (int g = 0; g < GG; g++) {
        redO[rg][g][d0+0] = o[g][0]; redO[rg][g][d0+1] = o[g][1];
        redO[rg][g][d0+2] = o[g][2]; redO[rg][g][d0+3] = o[g][3];
    }
    __syncthreads();

    int pb = ((b * KVHH) + kvh) * NCHUNK + c;
    if (t < GG) {
        g_pden[pb][t] = sredW[0 * 4 + t] + sredW[1 * 4 + t]
                      + sredW[2 * 4 + t] + sredW[3 * 4 + t];
    }
#pragma unroll
    for (int g = 0; g < GG; g++) {
        float num = redO[0][g][t] + redO[1][g][t] + redO[2][g][t] + redO[3][g][t];
        g_pnum[pb][g * DD + t] = num;
    }
}

// ---------------------------------------------------------------------------
// 4) Epilogue: sum chunk partials, divide, write [B, N]
// ---------------------------------------------------------------------------
__global__ void attn_epilogue(float* __restrict__ out) {
    int bk = blockIdx.x;   // b*KVHH + kvh
    int t  = threadIdx.x;  // 128
    int b = bk / KVHH, kvh = bk % KVHH;
#pragma unroll
    for (int g = 0; g < GG; g++) {
        float num = 0.f, den = 0.f;
#pragma unroll
        for (int c = 0; c < NCHUNK; c++) {
            int pb = bk * NCHUNK + c;
            num += g_pnum[pb][g * DD + t];
            den += g_pden[pb][g];
        }
        out[(size_t)b * NN + (kvh * GG + g) * DD + t] = num / den;
    }
}

// ---------------------------------------------------------------------------
extern "C" void kernel_launch(void* const* d_in, const int* in_sizes, int n_in,
                              void* d_out, int out_size) {
    const float* X  = (const float*)d_in[0];
    const float* Wq = (const float*)d_in[1];
    const float* Wk = (const float*)d_in[2];
    const float* Wv = (const float*)d_in[3];
    const float* cK = (const float*)d_in[4];
    const float* cV = (const float*)d_in[5];
    float* out = (float*)d_out;

    rms_kernel<<<BB, 256>>>(X);
    qkv_kernel<<<dim3(ROWS_TOT / 128, KSPLIT), 256>>>(X, Wq, Wk, Wv);
    attn_kernel<<<dim3(NCHUNK, KVHH, BB), 128>>>(cK, cV);
    attn_epilogue<<<BB * KVHH, 128>>>(out);
}